// round 10
// baseline (speedup 1.0000x reference)
#include <cuda_runtime.h>

#define TT 1024
#define BB 32
#define II 512
#define HH 512
#define GG 2048   // 4*H

struct __align__(16) u64x2 { unsigned long long a, b; };

__device__ __forceinline__ unsigned long long ffma2(
    unsigned long long x, unsigned long long y, unsigned long long z)
{
    unsigned long long r;
    asm("fma.rn.f32x2 %0, %1, %2, %3;" : "=l"(r) : "l"(x), "l"(y), "l"(z));
    return r;
}
__device__ __forceinline__ void unpack2(float& lo, float& hi, unsigned long long v)
{
    asm("mov.b64 {%0, %1}, %2;" : "=f"(lo), "=f"(hi) : "l"(v));
}
__device__ __forceinline__ unsigned ld_acq(const unsigned* p)
{
    unsigned v;
    asm volatile("ld.acquire.gpu.u32 %0, [%1];" : "=r"(v) : "l"(p) : "memory");
    return v;
}

// Scratch: gates_x in [t][g][b] layout (scan-friendly: lane=b coalesced)
__device__ float g_gates[(size_t)TT * GG * BB];
// Per-block progress flags: g_flag[b] = number of steps block b has completed.
// Monotonic within a launch; reset to 0 at kernel end (after a full barrier).
#define NBLK 128
__device__ unsigned int g_flag[NBLK];
__device__ unsigned int g_bar_count;
__device__ unsigned int g_bar_gen;

// ---------------------------------------------------------------------------
// Kernel 1: gates_x[t,b,g] = sum_i input[t,b,i] * W_ih[g,i] + b_ih[g] + b_hh[g]
// (R1 version, verbatim — measured ~1.37 ms)
// ---------------------------------------------------------------------------
#define BM 128
#define BN 128
#define BK 16
#define LDP 132

__global__ __launch_bounds__(256) void gemm_input(
    const float* __restrict__ A, const float* __restrict__ W,
    const float* __restrict__ b_ih, const float* __restrict__ b_hh)
{
    __shared__ __align__(16) float As[BK * LDP];
    __shared__ __align__(16) float Bs[BK * LDP];
    const int tid = threadIdx.x;
    const int m0 = blockIdx.y * BM;
    const int n0 = blockIdx.x * BN;
    const int tm = (tid >> 4) * 8;
    const int tn = (tid & 15) * 8;

    float acc[8][8];
#pragma unroll
    for (int i = 0; i < 8; i++)
#pragma unroll
        for (int j = 0; j < 8; j++) acc[i][j] = 0.f;

    for (int k0 = 0; k0 < II; k0 += BK) {
#pragma unroll
        for (int i = 0; i < 2; i++) {
            int f   = tid + i * 256;      // 0..511
            int row = f >> 2;             // 0..127
            int kq  = (f & 3) * 4;        // 0,4,8,12
            float4 va = *(const float4*)(A + (size_t)(m0 + row) * II + k0 + kq);
            As[(kq + 0) * LDP + row] = va.x;
            As[(kq + 1) * LDP + row] = va.y;
            As[(kq + 2) * LDP + row] = va.z;
            As[(kq + 3) * LDP + row] = va.w;
            float4 vb = *(const float4*)(W + (size_t)(n0 + row) * II + k0 + kq);
            Bs[(kq + 0) * LDP + row] = vb.x;
            Bs[(kq + 1) * LDP + row] = vb.y;
            Bs[(kq + 2) * LDP + row] = vb.z;
            Bs[(kq + 3) * LDP + row] = vb.w;
        }
        __syncthreads();
#pragma unroll
        for (int k = 0; k < BK; k++) {
            float a[8], bb[8];
            *(float4*)&a[0]  = *(float4*)&As[k * LDP + tm];
            *(float4*)&a[4]  = *(float4*)&As[k * LDP + tm + 4];
            *(float4*)&bb[0] = *(float4*)&Bs[k * LDP + tn];
            *(float4*)&bb[4] = *(float4*)&Bs[k * LDP + tn + 4];
#pragma unroll
            for (int i = 0; i < 8; i++)
#pragma unroll
                for (int j = 0; j < 8; j++) acc[i][j] += a[i] * bb[j];
        }
        __syncthreads();
    }

    float bj[8];
#pragma unroll
    for (int j = 0; j < 8; j++) {
        int g = n0 + tn + j;
        bj[j] = b_ih[g] + b_hh[g];
    }
#pragma unroll
    for (int i = 0; i < 8; i++) {
        int m = m0 + tm + i;
        int t = m >> 5, b = m & 31;
        size_t base = ((size_t)t * GG) * BB + (size_t)b;
#pragma unroll
        for (int j = 0; j < 8; j++) {
            int g = n0 + tn + j;
            g_gates[base + (size_t)g * BB] = acc[i][j] + bj[j];
        }
    }
}

// ---------------------------------------------------------------------------
// Kernel 2: persistent LSTM scan, 128 blocks x 256 threads.
// Compute mapping = R9 (proven). Sync = per-block progress flags:
//   - Warp kseg only needs h-cols [64k,64k+64) = blocks 16k..16k+15.
//     16 lanes acquire-poll 16 consecutive flags (coalesced 64B), then the
//     warp loads its 8KB h band into its warp-private h_sh band (syncwarp).
//   - Producer: bar.sync -> tid0 threadfence + flag[bid] = t+1.
//   Per-block flags checked individually => immune to run-ahead (the R6/R8
//   summed-counter bug). Cleanup uses the proven R1 grid barrier once.
// ---------------------------------------------------------------------------
#define NTHR 256
#define HP 516
#define WP 516
#define PCELL 36   // 4 gates x 8 ksegs = 32 floats + 4 pad

__device__ __forceinline__ void grid_barrier()
{
    __syncthreads();
    if (threadIdx.x == 0) {
        unsigned gen = *((volatile unsigned*)&g_bar_gen);
        __threadfence();
        if (atomicAdd(&g_bar_count, 1u) == NBLK - 1) {
            g_bar_count = 0;
            __threadfence();
            atomicAdd(&g_bar_gen, 1u);   // release
        } else {
            while (*((volatile unsigned*)&g_bar_gen) == gen) { }
        }
        __threadfence();
    }
    __syncthreads();
}

__global__ __launch_bounds__(NTHR) void lstm_scan(
    const float* __restrict__ h0, const float* __restrict__ c0,
    const float* __restrict__ W_hh, float* __restrict__ out, int out_size)
{
    extern __shared__ __align__(16) float smem[];
    float* W_sh = smem;                      // 16 * WP
    float* h_sh = smem + 16 * WP;            // 32 * HP
    float* part = smem + 16 * WP + 32 * HP;  // 128 * PCELL

    const int tid  = threadIdx.x;
    const int bid  = blockIdx.x;
    const int j0   = bid * 4;
    const int wid  = tid >> 5;
    const int lane = tid & 31;

    // Preload this block's W_hh slice once (time-invariant).
    for (int f4 = tid; f4 < 16 * 128; f4 += NTHR) {
        int c = f4 >> 7, k4 = f4 & 127;
        int gcol = (c >> 2) * HH + j0 + (c & 3);   // c = gate*4 + cidx
        *(float4*)&W_sh[c * WP + k4 * 4] =
            *(const float4*)&W_hh[(size_t)gcol * HH + k4 * 4];
    }

    // compute-role mapping
    const int kseg = wid;                  // 0..7
    const int k0   = kseg * 64;
    const int cidx = lane & 3;             // 0..3
    const int bg   = lane >> 2;            // 0..7; batches bg + 8*bb

    // h-band load mapping (warp-private band: cols [k0, k0+64), all 32 rows)
    const int f4i = lane & 15;             // float4 index within 64-col band
    const int rh  = lane >> 4;             // row parity

    // epilogue-role mapping (tid < 128): col j0+ue, batch be
    const int ue = tid >> 5;
    const int be = lane;

    float creg = 0.f, hreg = 0.f;
    if (tid < 128) creg = c0[be * HH + j0 + ue];

    float* outputs = out;   // [T][B][H]

    const float* hr[4];
    const float* wr[4];
#pragma unroll
    for (int bb = 0; bb < 4; bb++) hr[bb] = h_sh + (bg + 8 * bb) * HP + k0;
#pragma unroll
    for (int g = 0; g < 4; g++)    wr[g]  = W_sh + (g * 4 + cidx) * WP + k0;

    __syncthreads();   // W_sh ready (one-time)

    for (int t = 0; t < TT; t++) {
        const float* hp = (t == 0) ? h0 : (outputs + (size_t)(t - 1) * BB * HH);

        // Prefetch gates_x (DRAM) early; lands before the epilogue.
        float gxi = 0.f, gxf = 0.f, gxg = 0.f, gxo = 0.f;
        if (tid < 128) {
            const float* gx = g_gates + (size_t)t * GG * BB;
            gxi = gx[(size_t)(0 * HH + j0 + ue) * BB + be];
            gxf = gx[(size_t)(1 * HH + j0 + ue) * BB + be];
            gxg = gx[(size_t)(2 * HH + j0 + ue) * BB + be];
            gxo = gx[(size_t)(3 * HH + j0 + ue) * BB + be];
        }

        // Fine-grained wait: this warp needs blocks 16*kseg..16*kseg+15 at >= t.
        if (t > 0) {
            if (lane < 16) {
                const unsigned* f = &g_flag[(kseg << 4) + lane];
                while (ld_acq(f) < (unsigned)t) { }
            }
            __syncwarp();
        }

        // Warp loads its h band (cols [k0,k0+64), rows 0..31) into h_sh.
#pragma unroll
        for (int i = 0; i < 16; i++) {
            int b2 = 2 * i + rh;
            *(float4*)&h_sh[b2 * HP + k0 + 4 * f4i] =
                *(const float4*)&hp[(size_t)b2 * HH + k0 + 4 * f4i];
        }
        __syncwarp();   // band visible within the warp (sole consumer)

        // Partial dots: 4 gates x 4 batches over this warp's 64-k segment.
        unsigned long long acc[4][4];
#pragma unroll
        for (int g = 0; g < 4; g++)
#pragma unroll
            for (int bb = 0; bb < 4; bb++) acc[g][bb] = 0ull;

#pragma unroll 4
        for (int it = 0; it < 16; it++) {
            u64x2 hv[4];
#pragma unroll
            for (int bb = 0; bb < 4; bb++)
                hv[bb] = *(const u64x2*)(hr[bb] + it * 4);
#pragma unroll
            for (int g = 0; g < 4; g++) {
                u64x2 w = *(const u64x2*)(wr[g] + it * 4);
#pragma unroll
                for (int bb = 0; bb < 4; bb++) {
                    acc[g][bb] = ffma2(hv[bb].a, w.a, acc[g][bb]);
                    acc[g][bb] = ffma2(hv[bb].b, w.b, acc[g][bb]);
                }
            }
        }
#pragma unroll
        for (int g = 0; g < 4; g++)
#pragma unroll
            for (int bb = 0; bb < 4; bb++) {
                float lo, hi;
                unpack2(lo, hi, acc[g][bb]);
                part[(cidx * 32 + bg + 8 * bb) * PCELL + g * 8 + kseg] = lo + hi;
            }
        __syncthreads();   // partials ready

        if (tid < 128) {
            const float* cell = &part[(ue * 32 + be) * PCELL];
            float ai = gxi, af = gxf, ag = gxg, ao = gxo;
#pragma unroll
            for (int q = 0; q < 2; q++) {
                float4 p0 = *(const float4*)(cell + 0  + q * 4);
                float4 p1 = *(const float4*)(cell + 8  + q * 4);
                float4 p2 = *(const float4*)(cell + 16 + q * 4);
                float4 p3 = *(const float4*)(cell + 24 + q * 4);
                ai += p0.x + p0.y + p0.z + p0.w;
                af += p1.x + p1.y + p1.z + p1.w;
                ag += p2.x + p2.y + p2.z + p2.w;
                ao += p3.x + p3.y + p3.z + p3.w;
            }
            float ig  = 1.f / (1.f + __expf(-ai));
            float fg  = 1.f / (1.f + __expf(-af));
            float gg2 = tanhf(ag);
            float og  = 1.f / (1.f + __expf(-ao));
            creg = fg * creg + ig * gg2;
            hreg = og * tanhf(creg);
            outputs[(size_t)t * BB * HH + (size_t)be * HH + j0 + ue] = hreg;
        }
        __syncthreads();   // epilogue done: h_t stores issued, part reads done

        // Publish this block's step-t completion (per-block monotonic flag).
        if (tid == 0) {
            __threadfence();
            *((volatile unsigned*)&g_flag[bid]) = (unsigned)(t + 1);
        }
    }

    // Tail: h_f then c_f appended after outputs.
    if (tid < 128) {
        size_t off = (size_t)TT * BB * HH;
        if ((size_t)out_size >= off + 2u * BB * HH) {
            out[off + (size_t)be * HH + j0 + ue]           = hreg;
            out[off + BB * HH + (size_t)be * HH + j0 + ue] = creg;
        }
    }

    // Cleanup: full (proven) barrier, then each block resets its own flag so
    // the next graph replay starts from flags == 0. Kernel-exit ordering
    // guarantees visibility to the next launch.
    grid_barrier();
    if (tid == 0) {
        *((volatile unsigned*)&g_flag[bid]) = 0u;
        __threadfence();
    }
}

// ---------------------------------------------------------------------------
extern "C" void kernel_launch(void* const* d_in, const int* in_sizes, int n_in,
                              void* d_out, int out_size)
{
    const float* input = (const float*)d_in[0];
    const float* h0    = (const float*)d_in[1];
    const float* c0    = (const float*)d_in[2];
    const float* W_ih  = (const float*)d_in[3];
    const float* W_hh  = (const float*)d_in[4];
    const float* b_ih  = (const float*)d_in[5];
    const float* b_hh  = (const float*)d_in[6];

    size_t smem = (size_t)(16 * WP + 32 * HP + 128 * PCELL) * sizeof(float);
    cudaFuncSetAttribute(lstm_scan, cudaFuncAttributeMaxDynamicSharedMemorySize,
                         (int)smem);

    dim3 g1(GG / BN, (TT * BB) / BM);   // 16 x 256 blocks
    gemm_input<<<g1, 256>>>(input, W_ih, b_ih, b_hh);
    lstm_scan<<<NBLK, NTHR, smem>>>(h0, c0, W_hh, (float*)d_out, out_size);
}

// round 13
// speedup vs baseline: 1.4599x; 1.4599x over previous
#include <cuda_runtime.h>

#define TT 1024
#define BB 32
#define II 512
#define HH 512
#define GG 2048   // 4*H

struct __align__(16) u64x2 { unsigned long long a, b; };

__device__ __forceinline__ unsigned long long ffma2(
    unsigned long long x, unsigned long long y, unsigned long long z)
{
    unsigned long long r;
    asm("fma.rn.f32x2 %0, %1, %2, %3;" : "=l"(r) : "l"(x), "l"(y), "l"(z));
    return r;
}
__device__ __forceinline__ void unpack2(float& lo, float& hi, unsigned long long v)
{
    asm("mov.b64 {%0, %1}, %2;" : "=f"(lo), "=f"(hi) : "l"(v));
}

// Scratch: gates_x in [t][g][b] layout (scan-friendly: lane=b coalesced)
__device__ float g_gates[(size_t)TT * GG * BB];
// Hierarchical two-sided barrier state. Counters return to 0 every round
// (reset by the closing block BEFORE the generation bump), so graph replays
// always start from a deterministic state. g_bar_gen is monotonic and only
// ever compared relatively.
#define NGRP 8
#define GRPSZ 16           // NBLK / NGRP
__device__ unsigned int g_bar_grp[NGRP * 32];   // 128B apart
__device__ unsigned int g_bar_master;
__device__ unsigned int g_bar_gen;

// ---------------------------------------------------------------------------
// Kernel 1: gates_x[t,b,g] = sum_i input[t,b,i] * W_ih[g,i] + b_ih[g] + b_hh[g]
// (R1 version, verbatim — proven)
// ---------------------------------------------------------------------------
#define BM 128
#define BN 128
#define BK 16
#define LDP 132

__global__ __launch_bounds__(256) void gemm_input(
    const float* __restrict__ A, const float* __restrict__ W,
    const float* __restrict__ b_ih, const float* __restrict__ b_hh)
{
    __shared__ __align__(16) float As[BK * LDP];
    __shared__ __align__(16) float Bs[BK * LDP];
    const int tid = threadIdx.x;
    const int m0 = blockIdx.y * BM;
    const int n0 = blockIdx.x * BN;
    const int tm = (tid >> 4) * 8;
    const int tn = (tid & 15) * 8;

    float acc[8][8];
#pragma unroll
    for (int i = 0; i < 8; i++)
#pragma unroll
        for (int j = 0; j < 8; j++) acc[i][j] = 0.f;

    for (int k0 = 0; k0 < II; k0 += BK) {
#pragma unroll
        for (int i = 0; i < 2; i++) {
            int f   = tid + i * 256;      // 0..511
            int row = f >> 2;             // 0..127
            int kq  = (f & 3) * 4;        // 0,4,8,12
            float4 va = *(const float4*)(A + (size_t)(m0 + row) * II + k0 + kq);
            As[(kq + 0) * LDP + row] = va.x;
            As[(kq + 1) * LDP + row] = va.y;
            As[(kq + 2) * LDP + row] = va.z;
            As[(kq + 3) * LDP + row] = va.w;
            float4 vb = *(const float4*)(W + (size_t)(n0 + row) * II + k0 + kq);
            Bs[(kq + 0) * LDP + row] = vb.x;
            Bs[(kq + 1) * LDP + row] = vb.y;
            Bs[(kq + 2) * LDP + row] = vb.z;
            Bs[(kq + 3) * LDP + row] = vb.w;
        }
        __syncthreads();
#pragma unroll
        for (int k = 0; k < BK; k++) {
            float a[8], bb[8];
            *(float4*)&a[0]  = *(float4*)&As[k * LDP + tm];
            *(float4*)&a[4]  = *(float4*)&As[k * LDP + tm + 4];
            *(float4*)&bb[0] = *(float4*)&Bs[k * LDP + tn];
            *(float4*)&bb[4] = *(float4*)&Bs[k * LDP + tn + 4];
#pragma unroll
            for (int i = 0; i < 8; i++)
#pragma unroll
                for (int j = 0; j < 8; j++) acc[i][j] += a[i] * bb[j];
        }
        __syncthreads();
    }

    float bj[8];
#pragma unroll
    for (int j = 0; j < 8; j++) {
        int g = n0 + tn + j;
        bj[j] = b_ih[g] + b_hh[g];
    }
#pragma unroll
    for (int i = 0; i < 8; i++) {
        int m = m0 + tm + i;
        int t = m >> 5, b = m & 31;
        size_t base = ((size_t)t * GG) * BB + (size_t)b;
#pragma unroll
        for (int j = 0; j < 8; j++) {
            int g = n0 + tn + j;
            g_gates[base + (size_t)g * BB] = acc[i][j] + bj[j];
        }
    }
}

// ---------------------------------------------------------------------------
// Kernel 2: persistent LSTM scan, 128 blocks x 256 threads (R9 body, proven).
// Only change vs R9: hierarchical two-sided sense-reversing barrier.
//   arrivals: 16 atomics per group counter (8 groups in parallel)
//   group closer (old==15) -> 1 atomic on master
//   master closer (old==7) -> reset all counters, threadfence, bump gen
//   everyone spins on the single g_bar_gen word (one L2 line).
// All 128 round-r arrivals happen-before the reset (counter==16 per group,
// master==8), and no block can start round r+1 until gen bumps (after reset).
// ---------------------------------------------------------------------------
#define NBLK 128
#define NTHR 256
#define HP 516
#define WP 516
#define PCELL 36   // 4 gates x 8 ksegs = 32 floats + 4 pad

__device__ __forceinline__ void grid_barrier_h(int bid)
{
    __syncthreads();
    if (threadIdx.x == 0) {
        unsigned gen = *((volatile unsigned*)&g_bar_gen);
        __threadfence();
        unsigned old = atomicAdd(&g_bar_grp[(bid & (NGRP - 1)) << 5], 1u);
        if (old == GRPSZ - 1) {                    // closed this group
            unsigned old2 = atomicAdd(&g_bar_master, 1u);
            if (old2 == NGRP - 1) {                // closed the barrier
#pragma unroll
                for (int i = 0; i < NGRP; i++) g_bar_grp[i << 5] = 0u;
                g_bar_master = 0u;
                __threadfence();
                atomicAdd(&g_bar_gen, 1u);         // release
            } else {
                while (*((volatile unsigned*)&g_bar_gen) == gen) { }
            }
        } else {
            while (*((volatile unsigned*)&g_bar_gen) == gen) { }
        }
        __threadfence();
    }
    __syncthreads();
}

__global__ __launch_bounds__(NTHR) void lstm_scan(
    const float* __restrict__ h0, const float* __restrict__ c0,
    const float* __restrict__ W_hh, float* __restrict__ out, int out_size)
{
    extern __shared__ __align__(16) float smem[];
    float* W_sh = smem;                      // 16 * WP
    float* h_sh = smem + 16 * WP;            // 32 * HP
    float* part = smem + 16 * WP + 32 * HP;  // 128 * PCELL

    const int tid  = threadIdx.x;
    const int bid  = blockIdx.x;
    const int j0   = bid * 4;
    const int wid  = tid >> 5;
    const int lane = tid & 31;

    // Preload this block's W_hh slice once (time-invariant).
    for (int f4 = tid; f4 < 16 * 128; f4 += NTHR) {
        int c = f4 >> 7, k4 = f4 & 127;
        int gcol = (c >> 2) * HH + j0 + (c & 3);   // c = gate*4 + cidx
        *(float4*)&W_sh[c * WP + k4 * 4] =
            *(const float4*)&W_hh[(size_t)gcol * HH + k4 * 4];
    }

    // compute-role mapping
    const int kseg = wid;                  // 0..7
    const int k0   = kseg * 64;
    const int cidx = lane & 3;             // 0..3
    const int bg   = lane >> 2;            // 0..7; batches bg + 8*bb

    // epilogue-role mapping (tid < 128): col j0+ue, batch be
    const int ue = tid >> 5;
    const int be = lane;

    float creg = 0.f, hreg = 0.f;
    if (tid < 128) creg = c0[be * HH + j0 + ue];

    float* outputs = out;   // [T][B][H]

    const float* hr[4];
    const float* wr[4];
#pragma unroll
    for (int bb = 0; bb < 4; bb++) hr[bb] = h_sh + (bg + 8 * bb) * HP + k0;
#pragma unroll
    for (int g = 0; g < 4; g++)    wr[g]  = W_sh + (g * 4 + cidx) * WP + k0;

    for (int t = 0; t < TT; t++) {
        const float* hp = (t == 0) ? h0 : (outputs + (size_t)(t - 1) * BB * HH);

        // Prefetch gates_x (DRAM) early; lands before the epilogue.
        float gxi = 0.f, gxf = 0.f, gxg = 0.f, gxo = 0.f;
        if (tid < 128) {
            const float* gx = g_gates + (size_t)t * GG * BB;
            gxi = gx[(size_t)(0 * HH + j0 + ue) * BB + be];
            gxf = gx[(size_t)(1 * HH + j0 + ue) * BB + be];
            gxg = gx[(size_t)(2 * HH + j0 + ue) * BB + be];
            gxo = gx[(size_t)(3 * HH + j0 + ue) * BB + be];
        }

        // Cooperative load h_prev -> shared (h_{t-1} published by the
        // barrier at the end of step t-1; h0 for t==0).
#pragma unroll
        for (int r = 0; r < 16; r++) {
            int f4 = r * NTHR + tid;
            int b2 = f4 >> 7, k4 = f4 & 127;
            *(float4*)&h_sh[b2 * HP + k4 * 4] =
                *(const float4*)&hp[b2 * HH + k4 * 4];
        }
        __syncthreads();   // h_sh ready (also covers W_sh preload on t==0)

        // Partial dots: 4 gates x 4 batches over this warp's 64-k segment.
        unsigned long long acc[4][4];
#pragma unroll
        for (int g = 0; g < 4; g++)
#pragma unroll
            for (int bb = 0; bb < 4; bb++) acc[g][bb] = 0ull;

#pragma unroll 4
        for (int it = 0; it < 16; it++) {
            u64x2 hv[4];
#pragma unroll
            for (int bb = 0; bb < 4; bb++)
                hv[bb] = *(const u64x2*)(hr[bb] + it * 4);
#pragma unroll
            for (int g = 0; g < 4; g++) {
                u64x2 w = *(const u64x2*)(wr[g] + it * 4);
#pragma unroll
                for (int bb = 0; bb < 4; bb++) {
                    acc[g][bb] = ffma2(hv[bb].a, w.a, acc[g][bb]);
                    acc[g][bb] = ffma2(hv[bb].b, w.b, acc[g][bb]);
                }
            }
        }
#pragma unroll
        for (int g = 0; g < 4; g++)
#pragma unroll
            for (int bb = 0; bb < 4; bb++) {
                float lo, hi;
                unpack2(lo, hi, acc[g][bb]);
                part[(cidx * 32 + bg + 8 * bb) * PCELL + g * 8 + kseg] = lo + hi;
            }
        __syncthreads();   // partials ready

        if (tid < 128) {
            const float* cell = &part[(ue * 32 + be) * PCELL];
            float ai = gxi, af = gxf, ag = gxg, ao = gxo;
#pragma unroll
            for (int q = 0; q < 2; q++) {
                float4 p0 = *(const float4*)(cell + 0  + q * 4);
                float4 p1 = *(const float4*)(cell + 8  + q * 4);
                float4 p2 = *(const float4*)(cell + 16 + q * 4);
                float4 p3 = *(const float4*)(cell + 24 + q * 4);
                ai += p0.x + p0.y + p0.z + p0.w;
                af += p1.x + p1.y + p1.z + p1.w;
                ag += p2.x + p2.y + p2.z + p2.w;
                ao += p3.x + p3.y + p3.z + p3.w;
            }
            float ig  = 1.f / (1.f + __expf(-ai));
            float fg  = 1.f / (1.f + __expf(-af));
            float gg2 = tanhf(ag);
            float og  = 1.f / (1.f + __expf(-ao));
            creg = fg * creg + ig * gg2;
            hreg = og * tanhf(creg);
            outputs[(size_t)t * BB * HH + (size_t)be * HH + j0 + ue] = hreg;
        }
        grid_barrier_h(bid);   // publish h_t globally; protects h_sh/part reuse
    }

    // Tail: h_f then c_f appended after outputs.
    if (tid < 128) {
        size_t off = (size_t)TT * BB * HH;
        if ((size_t)out_size >= off + 2u * BB * HH) {
            out[off + (size_t)be * HH + j0 + ue]           = hreg;
            out[off + BB * HH + (size_t)be * HH + j0 + ue] = creg;
        }
    }
}

// ---------------------------------------------------------------------------
extern "C" void kernel_launch(void* const* d_in, const int* in_sizes, int n_in,
                              void* d_out, int out_size)
{
    const float* input = (const float*)d_in[0];
    const float* h0    = (const float*)d_in[1];
    const float* c0    = (const float*)d_in[2];
    const float* W_ih  = (const float*)d_in[3];
    const float* W_hh  = (const float*)d_in[4];
    const float* b_ih  = (const float*)d_in[5];
    const float* b_hh  = (const float*)d_in[6];

    size_t smem = (size_t)(16 * WP + 32 * HP + 128 * PCELL) * sizeof(float);
    cudaFuncSetAttribute(lstm_scan, cudaFuncAttributeMaxDynamicSharedMemorySize,
                         (int)smem);

    dim3 g1(GG / BN, (TT * BB) / BM);   // 16 x 256 blocks
    gemm_input<<<g1, 256>>>(input, W_ih, b_ih, b_hh);
    lstm_scan<<<NBLK, NTHR, smem>>>(h0, c0, W_hh, (float*)d_out, out_size);
}